// round 2
// baseline (speedup 1.0000x reference)
#include <cuda_runtime.h>
#include <cuda_bf16.h>
#include <math_constants.h>

// Problem constants (fixed by the reference): B=4, H=8, S=2048, D=3
#define BATCH 4
#define HEADS 8
#define SEQ   2048
#define NCHUNK 9          // q-chunks per (b,h) -> grid 32*9=288 CTAs (2 balanced waves)
#define QCHUNK 228        // ceil(2048/9)
#define NTHREADS 256

__device__ __forceinline__ float ex2f(float x) {
    float y;
    asm("ex2.approx.f32 %0, %1;" : "=f"(y) : "f"(x));
    return y;
}

__device__ __forceinline__ float rcpf(float x) {
    float y;
    asm("rcp.approx.f32 %0, %1;" : "=f"(y) : "f"(x));
    return y;
}

__global__ __launch_bounds__(NTHREADS)
void attn_kernel(const float* __restrict__ x,
                 const float* __restrict__ Wq,
                 const float* __restrict__ Wk,
                 const float* __restrict__ Wv,
                 float* __restrict__ out)
{
    // 48 KB static shared total: at the no-opt-in limit.
    __shared__ float4 sKV[SEQ];   // {k0, k1, k2, v0}
    __shared__ float2 sV[SEQ];    // {v1, v2}

    const int bh  = blockIdx.x;        // b*8 + h
    const int b   = bh >> 3;
    const int h   = bh & 7;
    const int tid = threadIdx.x;

    // Per-head 3x3 weights (broadcast LDG, L1/L2-cached).
    const float* wkp = Wk + h * 9;
    const float* wvp = Wv + h * 9;
    float wk[9], wv[9];
#pragma unroll
    for (int i = 0; i < 9; i++) { wk[i] = __ldg(wkp + i); wv[i] = __ldg(wvp + i); }

    const float* xb = x + b * SEQ * 3;

    // Build K and V for this (b,h) into shared memory.
    for (int s = tid; s < SEQ; s += NTHREADS) {
        const float x0 = xb[3 * s + 0];
        const float x1 = xb[3 * s + 1];
        const float x2 = xb[3 * s + 2];
        const float k0 = fmaf(x2, wk[6], fmaf(x1, wk[3], x0 * wk[0]));
        const float k1 = fmaf(x2, wk[7], fmaf(x1, wk[4], x0 * wk[1]));
        const float k2 = fmaf(x2, wk[8], fmaf(x1, wk[5], x0 * wk[2]));
        const float v0 = fmaf(x2, wv[6], fmaf(x1, wv[3], x0 * wv[0]));
        const float v1 = fmaf(x2, wv[7], fmaf(x1, wv[4], x0 * wv[1]));
        const float v2 = fmaf(x2, wv[8], fmaf(x1, wv[5], x0 * wv[2]));
        sKV[s] = make_float4(k0, k1, k2, v0);
        sV[s]  = make_float2(v1, v2);
    }
    __syncthreads();

    if (tid >= QCHUNK) return;
    const int q = blockIdx.y * QCHUNK + tid;
    if (q >= SEQ) return;

    // Query vector, pre-scaled by (1/sqrt(3)) * log2(e) so that
    // exp(scale * q.k) == exp2(q'.k). Monotone, so the pass-1 max is valid
    // in the same domain.
    const float cs = 1.4426950408889634f * 0.5773502691896258f; // log2(e)/sqrt(3)
    const float* wqp = Wq + h * 9;
    const float xq0 = xb[3 * q + 0];
    const float xq1 = xb[3 * q + 1];
    const float xq2 = xb[3 * q + 2];
    const float q0 = fmaf(xq2, __ldg(wqp + 6), fmaf(xq1, __ldg(wqp + 3), xq0 * __ldg(wqp + 0))) * cs;
    const float q1 = fmaf(xq2, __ldg(wqp + 7), fmaf(xq1, __ldg(wqp + 4), xq0 * __ldg(wqp + 1))) * cs;
    const float q2 = fmaf(xq2, __ldg(wqp + 8), fmaf(xq1, __ldg(wqp + 5), xq0 * __ldg(wqp + 2))) * cs;

    // Pass 1: row max in the exp2 domain.
    // 4 independent max accumulators break the FMNMX latency chain
    // (2048*4 cyc -> ~2048 cyc).
    float m0 = -CUDART_INF_F, m1 = -CUDART_INF_F;
    float m2 = -CUDART_INF_F, m3 = -CUDART_INF_F;
#pragma unroll 4
    for (int s = 0; s < SEQ; s += 4) {
        const float4 a = sKV[s + 0];
        const float4 c = sKV[s + 1];
        const float4 d = sKV[s + 2];
        const float4 e = sKV[s + 3];
        m0 = fmaxf(m0, fmaf(q2, a.z, fmaf(q1, a.y, q0 * a.x)));
        m1 = fmaxf(m1, fmaf(q2, c.z, fmaf(q1, c.y, q0 * c.x)));
        m2 = fmaxf(m2, fmaf(q2, d.z, fmaf(q1, d.y, q0 * d.x)));
        m3 = fmaxf(m3, fmaf(q2, e.z, fmaf(q1, e.y, q0 * e.x)));
    }
    const float m = fmaxf(fmaxf(m0, m1), fmaxf(m2, m3));

    // Pass 2: exp2-accumulate. -m folded into the dot accumulator seed.
    float den = 0.f, n0 = 0.f, n1 = 0.f, n2 = 0.f;
#pragma unroll 8
    for (int s = 0; s < SEQ; s++) {
        const float4 kv = sKV[s];
        const float2 v  = sV[s];
        const float t = fmaf(q0, kv.x, fmaf(q1, kv.y, fmaf(q2, kv.z, -m)));
        const float e = ex2f(t);
        den += e;
        n0 = fmaf(e, kv.w, n0);
        n1 = fmaf(e, v.x, n1);
        n2 = fmaf(e, v.y, n2);
    }

    const float inv = rcpf(den);
    const int base = (bh * SEQ + q) * 3;
    const int dup  = BATCH * HEADS * SEQ * 3;
    const float o0 = n0 * inv, o1 = n1 * inv, o2 = n2 * inv;
    out[base + 0] = o0;
    out[base + 1] = o1;
    out[base + 2] = o2;
    out[dup + base + 0] = o0;
    out[dup + base + 1] = o1;
    out[dup + base + 2] = o2;
}

extern "C" void kernel_launch(void* const* d_in, const int* in_sizes, int n_in,
                              void* d_out, int out_size)
{
    const float* x  = (const float*)d_in[0];
    const float* Wq = (const float*)d_in[1];
    const float* Wk = (const float*)d_in[2];
    const float* Wv = (const float*)d_in[3];
    float* out = (float*)d_out;

    dim3 grid(BATCH * HEADS, NCHUNK);
    attn_kernel<<<grid, NTHREADS>>>(x, Wq, Wk, Wv, out);
}

// round 3
// speedup vs baseline: 1.6223x; 1.6223x over previous
#include <cuda_runtime.h>
#include <cuda_bf16.h>
#include <math_constants.h>

// Problem constants (fixed by the reference): B=4, H=8, S=2048, D=3
#define BATCH 4
#define HEADS 8
#define SEQ   2048
#define NGROUP (SEQ / 4)  // 512 groups of 4 keys
#define NCHUNK 9          // q-chunks per (b,h) -> grid 32*9=288 CTAs (2 waves, 97% balance)
#define QCHUNK 228        // ceil(2048/9)
#define NTHREADS 256

typedef unsigned long long u64;

__device__ __forceinline__ float ex2f(float x) {
    float y; asm("ex2.approx.f32 %0, %1;" : "=f"(y) : "f"(x)); return y;
}
__device__ __forceinline__ float rcpf(float x) {
    float y; asm("rcp.approx.f32 %0, %1;" : "=f"(y) : "f"(x)); return y;
}
__device__ __forceinline__ u64 fma2(u64 a, u64 b, u64 c) {
    u64 d; asm("fma.rn.f32x2 %0, %1, %2, %3;" : "=l"(d) : "l"(a), "l"(b), "l"(c)); return d;
}
__device__ __forceinline__ u64 mul2(u64 a, u64 b) {
    u64 d; asm("mul.rn.f32x2 %0, %1, %2;" : "=l"(d) : "l"(a), "l"(b)); return d;
}
__device__ __forceinline__ u64 add2(u64 a, u64 b) {
    u64 d; asm("add.rn.f32x2 %0, %1, %2;" : "=l"(d) : "l"(a), "l"(b)); return d;
}
__device__ __forceinline__ u64 pack2(float lo, float hi) {
    u64 d; asm("mov.b64 %0, {%1, %2};" : "=l"(d) : "f"(lo), "f"(hi)); return d;
}
__device__ __forceinline__ void unpack2(u64 v, float& lo, float& hi) {
    asm("mov.b64 {%0, %1}, %2;" : "=f"(lo), "=f"(hi) : "l"(v));
}

__global__ __launch_bounds__(NTHREADS)
void attn_kernel(const float* __restrict__ x,
                 const float* __restrict__ Wq,
                 const float* __restrict__ Wk,
                 const float* __restrict__ Wv,
                 float* __restrict__ out)
{
    // SoA over 4-key groups; 6 * 8KB = 48KB static shared (at the limit).
    __shared__ float4 sK0[NGROUP], sK1[NGROUP], sK2[NGROUP];
    __shared__ float4 sV0[NGROUP], sV1[NGROUP], sV2[NGROUP];

    const int bh  = blockIdx.x;        // b*8 + h
    const int b   = bh >> 3;
    const int h   = bh & 7;
    const int tid = threadIdx.x;

    const float* wkp = Wk + h * 9;
    const float* wvp = Wv + h * 9;
    float wk[9], wv[9];
#pragma unroll
    for (int i = 0; i < 9; i++) { wk[i] = __ldg(wkp + i); wv[i] = __ldg(wvp + i); }

    const float* xb = x + b * SEQ * 3;

    // Build K,V in 4-key SoA packs. Each thread handles 2 groups of 4 keys.
#pragma unroll
    for (int g = tid; g < NGROUP; g += NTHREADS) {
        // 12 consecutive floats = x for keys 4g..4g+3 (16B-aligned).
        const float4* xp = reinterpret_cast<const float4*>(xb + 12 * g);
        const float4 xa = xp[0], xc = xp[1], xd = xp[2];
        const float X0[4] = { xa.x, xa.w, xc.z, xd.y };
        const float X1[4] = { xa.y, xc.x, xc.w, xd.z };
        const float X2[4] = { xa.z, xc.y, xd.x, xd.w };
        float4 K0, K1, K2, V0, V1, V2;
        float* k0 = &K0.x; float* k1 = &K1.x; float* k2 = &K2.x;
        float* v0 = &V0.x; float* v1 = &V1.x; float* v2 = &V2.x;
#pragma unroll
        for (int j = 0; j < 4; j++) {
            k0[j] = fmaf(X2[j], wk[6], fmaf(X1[j], wk[3], X0[j] * wk[0]));
            k1[j] = fmaf(X2[j], wk[7], fmaf(X1[j], wk[4], X0[j] * wk[1]));
            k2[j] = fmaf(X2[j], wk[8], fmaf(X1[j], wk[5], X0[j] * wk[2]));
            v0[j] = fmaf(X2[j], wv[6], fmaf(X1[j], wv[3], X0[j] * wv[0]));
            v1[j] = fmaf(X2[j], wv[7], fmaf(X1[j], wv[4], X0[j] * wv[1]));
            v2[j] = fmaf(X2[j], wv[8], fmaf(X1[j], wv[5], X0[j] * wv[2]));
        }
        sK0[g] = K0; sK1[g] = K1; sK2[g] = K2;
        sV0[g] = V0; sV1[g] = V1; sV2[g] = V2;
    }
    __syncthreads();

    if (tid >= QCHUNK) return;
    const int q = blockIdx.y * QCHUNK + tid;
    if (q >= SEQ) return;

    // Query, pre-scaled by log2(e)/sqrt(3): exp(scale*q.k) == exp2(q'.k).
    // No row-max pass: |q'.k| is bounded far below float exp2 limits (see theory),
    // and softmax is invariant to the (omitted) uniform shift.
    const float cs = 1.4426950408889634f * 0.5773502691896258f;
    const float* wqp = Wq + h * 9;
    const float xq0 = xb[3 * q + 0];
    const float xq1 = xb[3 * q + 1];
    const float xq2 = xb[3 * q + 2];
    const float q0 = fmaf(xq2, __ldg(wqp + 6), fmaf(xq1, __ldg(wqp + 3), xq0 * __ldg(wqp + 0))) * cs;
    const float q1 = fmaf(xq2, __ldg(wqp + 7), fmaf(xq1, __ldg(wqp + 4), xq0 * __ldg(wqp + 1))) * cs;
    const float q2 = fmaf(xq2, __ldg(wqp + 8), fmaf(xq1, __ldg(wqp + 5), xq0 * __ldg(wqp + 2))) * cs;

    const u64 q0p = pack2(q0, q0);
    const u64 q1p = pack2(q1, q1);
    const u64 q2p = pack2(q2, q2);

    const ulonglong2* pK0 = reinterpret_cast<const ulonglong2*>(sK0);
    const ulonglong2* pK1 = reinterpret_cast<const ulonglong2*>(sK1);
    const ulonglong2* pK2 = reinterpret_cast<const ulonglong2*>(sK2);
    const ulonglong2* pV0 = reinterpret_cast<const ulonglong2*>(sV0);
    const ulonglong2* pV1 = reinterpret_cast<const ulonglong2*>(sV1);
    const ulonglong2* pV2 = reinterpret_cast<const ulonglong2*>(sV2);

    u64 dl = 0, dh = 0;              // 0ull == pack2(0.f, 0.f)
    u64 a0l = 0, a0h = 0, a1l = 0, a1h = 0, a2l = 0, a2h = 0;

#pragma unroll 4
    for (int i = 0; i < NGROUP; i++) {
        const ulonglong2 k0 = pK0[i];
        const ulonglong2 k1 = pK1[i];
        const ulonglong2 k2 = pK2[i];
        const ulonglong2 v0 = pV0[i];
        const ulonglong2 v1 = pV1[i];
        const ulonglong2 v2 = pV2[i];

        const u64 tl = fma2(q0p, k0.x, fma2(q1p, k1.x, mul2(q2p, k2.x)));
        const u64 th = fma2(q0p, k0.y, fma2(q1p, k1.y, mul2(q2p, k2.y)));

        float t0, t1, t2, t3;
        unpack2(tl, t0, t1);
        unpack2(th, t2, t3);
        const u64 el = pack2(ex2f(t0), ex2f(t1));
        const u64 eh = pack2(ex2f(t2), ex2f(t3));

        dl  = add2(dl, el);           dh  = add2(dh, eh);
        a0l = fma2(el, v0.x, a0l);    a0h = fma2(eh, v0.y, a0h);
        a1l = fma2(el, v1.x, a1l);    a1h = fma2(eh, v1.y, a1h);
        a2l = fma2(el, v2.x, a2l);    a2h = fma2(eh, v2.y, a2h);
    }

    float u0, u1, u2, u3;
    unpack2(dl, u0, u1); unpack2(dh, u2, u3);
    const float den = (u0 + u1) + (u2 + u3);
    unpack2(a0l, u0, u1); unpack2(a0h, u2, u3);
    const float n0 = (u0 + u1) + (u2 + u3);
    unpack2(a1l, u0, u1); unpack2(a1h, u2, u3);
    const float n1 = (u0 + u1) + (u2 + u3);
    unpack2(a2l, u0, u1); unpack2(a2h, u2, u3);
    const float n2 = (u0 + u1) + (u2 + u3);

    const float inv = rcpf(den);
    const int base = (bh * SEQ + q) * 3;
    const int dup  = BATCH * HEADS * SEQ * 3;
    const float o0 = n0 * inv, o1 = n1 * inv, o2 = n2 * inv;
    out[base + 0] = o0;
    out[base + 1] = o1;
    out[base + 2] = o2;
    out[dup + base + 0] = o0;
    out[dup + base + 1] = o1;
    out[dup + base + 2] = o2;
}

extern "C" void kernel_launch(void* const* d_in, const int* in_sizes, int n_in,
                              void* d_out, int out_size)
{
    const float* x  = (const float*)d_in[0];
    const float* Wq = (const float*)d_in[1];
    const float* Wk = (const float*)d_in[2];
    const float* Wv = (const float*)d_in[3];
    float* out = (float*)d_out;

    dim3 grid(BATCH * HEADS, NCHUNK);
    attn_kernel<<<grid, NTHREADS>>>(x, Wq, Wk, Wv, out);
}